// round 16
// baseline (speedup 1.0000x reference)
#include <cuda_runtime.h>
#include <cuda_fp16.h>
#include <cstdint>

// ======================= problem constants =======================
#define SEQ      8192
#define HD       128
#define MT       64                  // M tile (rows of S per CTA)
#define KT       64                  // K tile (cols of S per iteration)
#define KSPLITS  8
#define KCOLS    (SEQ / KSPLITS)     // 1024 cols per split
#define NTILES   (KCOLS / KT)        // 16 iterations per CTA
#define THREADS  256
#define MBLOCKS  (SEQ / MT)          // 128

#define PSTRIDE_H   72               // halves per smem row (64 data + 8 pad)
#define PSTRIDE_B   (PSTRIDE_H * 2)  // 144 bytes
#define PTILE_BYTES (MT  * PSTRIDE_B)   // 9216 B  (P tile: 64 rows)
#define VTILE_BYTES (128 * PSTRIDE_B)   // 18432 B (V tile: 128 rows)
#define SM_TOTAL    (2 * PTILE_BYTES + 2 * VTILE_BYTES)  // 55296 B

// ======================= device scratch (no cudaMalloc allowed) ==
__device__ float        g_Opart[KSPLITS][SEQ * HD];   // 32 MB partial numerators
__device__ float        g_lpart[KSPLITS][SEQ];        // partial denominators
__device__ __half       g_Vh[HD * SEQ];               // V_T pre-converted to fp16
__device__ unsigned int g_counter[MBLOCKS];           // split-arrival counters

// ======================= PTX helpers =============================
__device__ __forceinline__ uint32_t smem_u32(const void* p) {
    uint32_t a;
    asm("{ .reg .u64 t; cvta.to.shared.u64 t, %1; cvt.u32.u64 %0, t; }" : "=r"(a) : "l"(p));
    return a;
}

__device__ __forceinline__ void ldmatrix_x4(uint32_t* r, uint32_t addr) {
    asm volatile("ldmatrix.sync.aligned.m8n8.x4.shared.b16 {%0,%1,%2,%3}, [%4];"
                 : "=r"(r[0]), "=r"(r[1]), "=r"(r[2]), "=r"(r[3]) : "r"(addr));
}

__device__ __forceinline__ void mma16816(float* c, const uint32_t* a, const uint32_t* b) {
    asm volatile("mma.sync.aligned.m16n8k16.row.col.f32.f16.f16.f32 "
                 "{%0,%1,%2,%3}, {%4,%5,%6,%7}, {%8,%9}, {%0,%1,%2,%3};"
                 : "+f"(c[0]), "+f"(c[1]), "+f"(c[2]), "+f"(c[3])
                 : "r"(a[0]), "r"(a[1]), "r"(a[2]), "r"(a[3]), "r"(b[0]), "r"(b[1]));
}

#define CP_ASYNC16(dst, src) \
    asm volatile("cp.async.cg.shared.global [%0], [%1], 16;" :: "r"(dst), "l"(src))
#define CP_COMMIT() asm volatile("cp.async.commit_group;" ::: "memory")
#define CP_WAIT(n)  asm volatile("cp.async.wait_group %0;" :: "n"(n) : "memory")

// ======================= kernel 1: V convert + zero counters =====
__global__ void convert_v_kernel(const float* __restrict__ VT) {
    const int base = (blockIdx.x * blockDim.x + threadIdx.x) * 4;
    const int stride = gridDim.x * blockDim.x * 4;
    float4 v[4];
#pragma unroll
    for (int j = 0; j < 4; j++)
        v[j] = *reinterpret_cast<const float4*>(VT + base + j * stride);
#pragma unroll
    for (int j = 0; j < 4; j++) {
        union { __half2 h[2]; uint2 u; } c;
        c.h[0] = __floats2half2_rn(v[j].x, v[j].y);
        c.h[1] = __floats2half2_rn(v[j].z, v[j].w);
        *reinterpret_cast<uint2*>(&g_Vh[base + j * stride]) = c.u;
    }
    if (blockIdx.x == 0 && threadIdx.x < MBLOCKS)
        g_counter[threadIdx.x] = 0u;
}

// ======================= kernel 2: main streaming flash ==========
__global__ void __launch_bounds__(THREADS, 2)
flash_main_kernel(const float* __restrict__ S, float* __restrict__ out) {
    extern __shared__ char smem[];
    const int tid = threadIdx.x;
    const int lid = tid & 31;
    const int wid = tid >> 5;
    const int m0 = blockIdx.x * MT;
    const int ks = blockIdx.y;
    const int k0 = ks * KCOLS;

    char* pbuf[2] = { smem,                   smem + PTILE_BYTES };
    char* vbuf[2] = { smem + 2 * PTILE_BYTES, smem + 2 * PTILE_BYTES + VTILE_BYTES };

    // ---- S load mapping: 64 rows x 16 float4 per row; each thread 4 rows
    const int su  = tid & 15;        // float4 slot within row
    const int sr0 = tid >> 4;        // base row (0..15); rows sr0 + 16*j
    // ---- V load mapping: 128 rows x 8 uint4 per row; each thread 4 rows
    const int vu  = tid & 7;
    const int vr0 = tid >> 3;        // 0..31; rows vr0 + 32*j

    const float* Srow[4];
#pragma unroll
    for (int j = 0; j < 4; j++)
        Srow[j] = S + (size_t)(m0 + sr0 + 16 * j) * SEQ + k0 + su * 4;

    float rs[4] = {0.f, 0.f, 0.f, 0.f};

    // ---- prologue: depth-2 S prefetch + V(0) cp.async
    // stage[p] holds S(t) for t with t&1 == p.
    float4 stage[2][4];
#pragma unroll
    for (int j = 0; j < 4; j++)
        stage[0][j] = __ldcs(reinterpret_cast<const float4*>(Srow[j]));
    {
        const __half* vsrc = g_Vh + (size_t)vr0 * SEQ + k0 + vu * 8;
#pragma unroll
        for (int j = 0; j < 4; j++)
            CP_ASYNC16(smem_u32(vbuf[0] + (vr0 + 32 * j) * PSTRIDE_B + vu * 16),
                       vsrc + (size_t)(32 * j) * SEQ);
        CP_COMMIT();
    }
#pragma unroll
    for (int j = 0; j < 4; j++)
        stage[1][j] = __ldcs(reinterpret_cast<const float4*>(Srow[j] + KT));

    float acc[2][4][4];
#pragma unroll
    for (int a = 0; a < 2; a++)
#pragma unroll
        for (int b = 0; b < 4; b++)
#pragma unroll
            for (int c = 0; c < 4; c++) acc[a][b][c] = 0.0f;

    const int wm = wid >> 2;         // 0..1: 32-row band
    const int wn = wid & 3;          // 0..3: 32-col band

#pragma unroll 2
    for (int t = 0; t < NTILES; t++) {
        const int cur = t & 1;
        const int p   = t & 1;       // stage slot holding S(t)

        // ---- prefetch V(t+1) into other buffer; wait for V(t)
        if (t < NTILES - 1) {
            const __half* vsrc = g_Vh + (size_t)vr0 * SEQ + k0 + (t + 1) * KT + vu * 8;
#pragma unroll
            for (int j = 0; j < 4; j++)
                CP_ASYNC16(smem_u32(vbuf[cur ^ 1] + (vr0 + 32 * j) * PSTRIDE_B + vu * 16),
                           vsrc + (size_t)(32 * j) * SEQ);
            CP_COMMIT();
            CP_WAIT(1);
        } else {
            CP_WAIT(0);
        }

        // ---- convert S(t): exp -> fp16 -> pbuf[cur]; accumulate row sums
#pragma unroll
        for (int j = 0; j < 4; j++) {
            float e0 = __expf(stage[p][j].x), e1 = __expf(stage[p][j].y);
            float e2 = __expf(stage[p][j].z), e3 = __expf(stage[p][j].w);
            rs[j] += (e0 + e1) + (e2 + e3);
            union { __half2 h[2]; uint2 u; } c;
            c.h[0] = __floats2half2_rn(e0, e1);
            c.h[1] = __floats2half2_rn(e2, e3);
            *reinterpret_cast<uint2*>(pbuf[cur] + (sr0 + 16 * j) * PSTRIDE_B + su * 8) = c.u;
        }
        // ---- issue S(t+2) into the stage slot just consumed (2-iter cover)
        if (t < NTILES - 2) {
#pragma unroll
            for (int j = 0; j < 4; j++)
                stage[p][j] = __ldcs(reinterpret_cast<const float4*>(Srow[j] + (t + 2) * KT));
        }
        __syncthreads();

        // ---- MMA(t): warp (wm, wn) computes 32x32 over K=64
        const uint32_t pB = smem_u32(pbuf[cur]);
        const uint32_t vB = smem_u32(vbuf[cur]);
#pragma unroll
        for (int kk = 0; kk < 4; kk++) {
            uint32_t a[2][4];
#pragma unroll
            for (int mt = 0; mt < 2; mt++) {
                uint32_t addr = pB + (wm * 32 + mt * 16 + (lid & 15)) * PSTRIDE_B
                                   + (kk * 16 + (lid >> 4) * 8) * 2;
                ldmatrix_x4(a[mt], addr);
            }
#pragma unroll
            for (int np = 0; np < 2; np++) {
                uint32_t b[4];
                const int n    = wn * 32 + np * 16 + (lid >> 4) * 8 + (lid & 7);
                const int koff = kk * 16 + ((lid >> 3) & 1) * 8;
                ldmatrix_x4(b, vB + n * PSTRIDE_B + koff * 2);
#pragma unroll
                for (int mt = 0; mt < 2; mt++) {
                    mma16816(acc[mt][np * 2 + 0], a[mt], b + 0);
                    mma16816(acc[mt][np * 2 + 1], a[mt], b + 2);
                }
            }
        }
        __syncthreads();
    }

    // ---- row-sum partials: reduce over the 16-lane row group
#pragma unroll
    for (int j = 0; j < 4; j++) {
        float v = rs[j];
        v += __shfl_xor_sync(0xffffffffu, v, 8);
        v += __shfl_xor_sync(0xffffffffu, v, 4);
        v += __shfl_xor_sync(0xffffffffu, v, 2);
        v += __shfl_xor_sync(0xffffffffu, v, 1);
        if ((lid & 15) == 0)
            __stcg(&g_lpart[ks][m0 + sr0 + 16 * j], v);
    }

    // ---- store partial numerators (L2 streaming; no L1 residency)
    float* op = g_Opart[ks];
#pragma unroll
    for (int mt = 0; mt < 2; mt++) {
#pragma unroll
        for (int nt = 0; nt < 4; nt++) {
            const int row = m0 + wm * 32 + mt * 16 + (lid >> 2);
            const int col = wn * 32 + nt * 8 + (lid & 3) * 2;
            __stcg(reinterpret_cast<float2*>(&op[(size_t)row * HD + col]),
                   make_float2(acc[mt][nt][0], acc[mt][nt][1]));
            __stcg(reinterpret_cast<float2*>(&op[(size_t)(row + 8) * HD + col]),
                   make_float2(acc[mt][nt][2], acc[mt][nt][3]));
        }
    }

    // ---- fused combine: last-arriving split CTA per m-block.
    // Publication via release-sequence RMW chain on g_counter (no
    // __threadfence -> no CCTL.IVALL L1 flush). All partials were
    // written with stcg (L2) and are read below with ldcg (L2), so
    // L1 staleness cannot occur; bar.sync + thread-0 acq_rel atomic
    // gives the happens-before chain across the 8 split CTAs.
    __shared__ unsigned int s_old;
    __syncthreads();                 // all threads' stcg issued before atom
    if (tid == 0) {
        unsigned int o;
        asm volatile("atom.acq_rel.gpu.add.u32 %0, [%1], %2;"
                     : "=r"(o) : "l"(&g_counter[blockIdx.x]), "r"(1u) : "memory");
        s_old = o;
    }
    __syncthreads();
    if (s_old == KSPLITS - 1) {
        // combine rows [m0, m0+MT): 64*32 = 2048 float4, 8 per thread
        for (int i = tid; i < MT * HD / 4; i += THREADS) {
            const int row = i >> 5;              // /(HD/4)
            const size_t idx = (size_t)(m0 + row) * HD + (i & 31) * 4;
            float4 accv = make_float4(0.f, 0.f, 0.f, 0.f);
            float l = 0.0f;
#pragma unroll
            for (int s = 0; s < KSPLITS; s++) {
                float4 pv = __ldcg(reinterpret_cast<const float4*>(&g_Opart[s][idx]));
                accv.x += pv.x; accv.y += pv.y; accv.z += pv.z; accv.w += pv.w;
                l += __ldcg(&g_lpart[s][m0 + row]);
            }
            const float inv = 1.0f / l;
            accv.x *= inv; accv.y *= inv; accv.z *= inv; accv.w *= inv;
            *reinterpret_cast<float4*>(out + idx) = accv;
        }
    }
}

// ======================= launch ==================================
extern "C" void kernel_launch(void* const* d_in, const int* in_sizes, int n_in,
                              void* d_out, int out_size) {
    const float* S  = (const float*)d_in[0];   // [8192, 8192]
    const float* VT = (const float*)d_in[1];   // [128, 8192]
    float* out = (float*)d_out;                // [8192, 128]

    cudaFuncSetAttribute(flash_main_kernel,
                         cudaFuncAttributeMaxDynamicSharedMemorySize, SM_TOTAL);

    convert_v_kernel<<<(HD * SEQ) / (256 * 16), 256>>>(VT);
    dim3 grid(SEQ / MT, KSPLITS);
    flash_main_kernel<<<grid, THREADS, SM_TOTAL>>>(S, out);
}

// round 17
// speedup vs baseline: 1.0435x; 1.0435x over previous
#include <cuda_runtime.h>
#include <cuda_fp16.h>
#include <cstdint>

// ======================= problem constants =======================
#define SEQ      8192
#define HD       128
#define MT       64                  // M tile (rows of S per CTA)
#define KT       64                  // K tile (cols of S per iteration)
#define KSPLITS  8
#define KCOLS    (SEQ / KSPLITS)     // 1024 cols per split
#define NTILES   (KCOLS / KT)        // 16 iterations per CTA
#define THREADS  256

#define PSTRIDE_H   72               // halves per smem row (64 data + 8 pad)
#define PSTRIDE_B   (PSTRIDE_H * 2)  // 144 bytes
#define PTILE_BYTES (MT  * PSTRIDE_B)   // 9216 B  (P tile: 64 rows)
#define VTILE_BYTES (128 * PSTRIDE_B)   // 18432 B (V tile: 128 rows)
#define SM_TOTAL    (2 * PTILE_BYTES + 2 * VTILE_BYTES)  // 55296 B

// ======================= device scratch (no cudaMalloc allowed) ==
__device__ float  g_Opart[KSPLITS][SEQ * HD];   // 32 MB partial numerators
__device__ float  g_lpart[KSPLITS][SEQ];        // partial denominators
__device__ __half g_Vh[HD * SEQ];               // V_T pre-converted to fp16

// ======================= PTX helpers =============================
__device__ __forceinline__ uint32_t smem_u32(const void* p) {
    uint32_t a;
    asm("{ .reg .u64 t; cvta.to.shared.u64 t, %1; cvt.u32.u64 %0, t; }" : "=r"(a) : "l"(p));
    return a;
}

__device__ __forceinline__ void ldmatrix_x4(uint32_t* r, uint32_t addr) {
    asm volatile("ldmatrix.sync.aligned.m8n8.x4.shared.b16 {%0,%1,%2,%3}, [%4];"
                 : "=r"(r[0]), "=r"(r[1]), "=r"(r[2]), "=r"(r[3]) : "r"(addr));
}

__device__ __forceinline__ void mma16816(float* c, const uint32_t* a, const uint32_t* b) {
    asm volatile("mma.sync.aligned.m16n8k16.row.col.f32.f16.f16.f32 "
                 "{%0,%1,%2,%3}, {%4,%5,%6,%7}, {%8,%9}, {%0,%1,%2,%3};"
                 : "+f"(c[0]), "+f"(c[1]), "+f"(c[2]), "+f"(c[3])
                 : "r"(a[0]), "r"(a[1]), "r"(a[2]), "r"(a[3]), "r"(b[0]), "r"(b[1]));
}

#define CP_ASYNC16(dst, src) \
    asm volatile("cp.async.cg.shared.global [%0], [%1], 16;" :: "r"(dst), "l"(src))
#define CP_COMMIT() asm volatile("cp.async.commit_group;" ::: "memory")
#define CP_WAIT(n)  asm volatile("cp.async.wait_group %0;" :: "n"(n) : "memory")

// ======================= kernel 1: V_T fp32 -> fp16 (max TLP) ====
// 1024 blocks x 256 threads, one float4 per thread: 262144 threads
// fill the chip's thread slots; single-load latency hidden by TLP.
__global__ void convert_v_kernel(const float* __restrict__ VT) {
    const int i = (blockIdx.x * blockDim.x + threadIdx.x) * 4;
    float4 v = *reinterpret_cast<const float4*>(VT + i);
    union { __half2 h[2]; uint2 u; } c;
    c.h[0] = __floats2half2_rn(v.x, v.y);
    c.h[1] = __floats2half2_rn(v.z, v.w);
    *reinterpret_cast<uint2*>(&g_Vh[i]) = c.u;
}

// ======================= kernel 2: main streaming flash ==========
__global__ void __launch_bounds__(THREADS, 2)
flash_main_kernel(const float* __restrict__ S) {
    extern __shared__ char smem[];
    const int tid = threadIdx.x;
    const int lid = tid & 31;
    const int wid = tid >> 5;
    const int m0 = blockIdx.x * MT;
    const int ks = blockIdx.y;
    const int k0 = ks * KCOLS;

    char* pbuf[2] = { smem,                   smem + PTILE_BYTES };
    char* vbuf[2] = { smem + 2 * PTILE_BYTES, smem + 2 * PTILE_BYTES + VTILE_BYTES };

    // ---- S load mapping: 64 rows x 16 float4 per row; each thread 4 rows
    const int su  = tid & 15;        // float4 slot within row
    const int sr0 = tid >> 4;        // base row (0..15); rows sr0 + 16*j
    // ---- V load mapping: 128 rows x 8 uint4 per row; each thread 4 rows
    const int vu  = tid & 7;
    const int vr0 = tid >> 3;        // 0..31; rows vr0 + 32*j

    const float* Srow[4];
#pragma unroll
    for (int j = 0; j < 4; j++)
        Srow[j] = S + (size_t)(m0 + sr0 + 16 * j) * SEQ + k0 + su * 4;

    float rs[4] = {0.f, 0.f, 0.f, 0.f};

    // ---- prologue: depth-2 S prefetch + V(0) cp.async
    // stage[p] holds S(t) for t with t&1 == p.
    float4 stage[2][4];
#pragma unroll
    for (int j = 0; j < 4; j++)
        stage[0][j] = __ldcs(reinterpret_cast<const float4*>(Srow[j]));
    {
        const __half* vsrc = g_Vh + (size_t)vr0 * SEQ + k0 + vu * 8;
#pragma unroll
        for (int j = 0; j < 4; j++)
            CP_ASYNC16(smem_u32(vbuf[0] + (vr0 + 32 * j) * PSTRIDE_B + vu * 16),
                       vsrc + (size_t)(32 * j) * SEQ);
        CP_COMMIT();
    }
#pragma unroll
    for (int j = 0; j < 4; j++)
        stage[1][j] = __ldcs(reinterpret_cast<const float4*>(Srow[j] + KT));

    float acc[2][4][4];
#pragma unroll
    for (int a = 0; a < 2; a++)
#pragma unroll
        for (int b = 0; b < 4; b++)
#pragma unroll
            for (int c = 0; c < 4; c++) acc[a][b][c] = 0.0f;

    const int wm = wid >> 2;         // 0..1: 32-row band
    const int wn = wid & 3;          // 0..3: 32-col band

#pragma unroll 2
    for (int t = 0; t < NTILES; t++) {
        const int cur = t & 1;
        const int p   = t & 1;       // stage slot holding S(t)

        // ---- prefetch V(t+1) into other buffer; wait for V(t)
        if (t < NTILES - 1) {
            const __half* vsrc = g_Vh + (size_t)vr0 * SEQ + k0 + (t + 1) * KT + vu * 8;
#pragma unroll
            for (int j = 0; j < 4; j++)
                CP_ASYNC16(smem_u32(vbuf[cur ^ 1] + (vr0 + 32 * j) * PSTRIDE_B + vu * 16),
                           vsrc + (size_t)(32 * j) * SEQ);
            CP_COMMIT();
            CP_WAIT(1);
        } else {
            CP_WAIT(0);
        }

        // ---- convert S(t): exp -> fp16 -> pbuf[cur]; accumulate row sums
#pragma unroll
        for (int j = 0; j < 4; j++) {
            float e0 = __expf(stage[p][j].x), e1 = __expf(stage[p][j].y);
            float e2 = __expf(stage[p][j].z), e3 = __expf(stage[p][j].w);
            rs[j] += (e0 + e1) + (e2 + e3);
            union { __half2 h[2]; uint2 u; } c;
            c.h[0] = __floats2half2_rn(e0, e1);
            c.h[1] = __floats2half2_rn(e2, e3);
            *reinterpret_cast<uint2*>(pbuf[cur] + (sr0 + 16 * j) * PSTRIDE_B + su * 8) = c.u;
        }
        // ---- issue S(t+2) into the stage slot just consumed (2-iter cover)
        if (t < NTILES - 2) {
#pragma unroll
            for (int j = 0; j < 4; j++)
                stage[p][j] = __ldcs(reinterpret_cast<const float4*>(Srow[j] + (t + 2) * KT));
        }
        __syncthreads();

        // ---- MMA(t): warp (wm, wn) computes 32x32 over K=64
        const uint32_t pB = smem_u32(pbuf[cur]);
        const uint32_t vB = smem_u32(vbuf[cur]);
#pragma unroll
        for (int kk = 0; kk < 4; kk++) {
            uint32_t a[2][4];
#pragma unroll
            for (int mt = 0; mt < 2; mt++) {
                uint32_t addr = pB + (wm * 32 + mt * 16 + (lid & 15)) * PSTRIDE_B
                                   + (kk * 16 + (lid >> 4) * 8) * 2;
                ldmatrix_x4(a[mt], addr);
            }
#pragma unroll
            for (int np = 0; np < 2; np++) {
                uint32_t b[4];
                const int n    = wn * 32 + np * 16 + (lid >> 4) * 8 + (lid & 7);
                const int koff = kk * 16 + ((lid >> 3) & 1) * 8;
                ldmatrix_x4(b, vB + n * PSTRIDE_B + koff * 2);
#pragma unroll
                for (int mt = 0; mt < 2; mt++) {
                    mma16816(acc[mt][np * 2 + 0], a[mt], b + 0);
                    mma16816(acc[mt][np * 2 + 1], a[mt], b + 2);
                }
            }
        }
        __syncthreads();
    }

    // ---- row-sum partials: reduce over the 16-lane row group
#pragma unroll
    for (int j = 0; j < 4; j++) {
        float v = rs[j];
        v += __shfl_xor_sync(0xffffffffu, v, 8);
        v += __shfl_xor_sync(0xffffffffu, v, 4);
        v += __shfl_xor_sync(0xffffffffu, v, 2);
        v += __shfl_xor_sync(0xffffffffu, v, 1);
        if ((lid & 15) == 0)
            g_lpart[ks][m0 + sr0 + 16 * j] = v;
    }

    // ---- store partial numerators (streaming: keep L2 for S)
    float* op = g_Opart[ks];
#pragma unroll
    for (int mt = 0; mt < 2; mt++) {
#pragma unroll
        for (int nt = 0; nt < 4; nt++) {
            const int row = m0 + wm * 32 + mt * 16 + (lid >> 2);
            const int col = wn * 32 + nt * 8 + (lid & 3) * 2;
            __stcg(reinterpret_cast<float2*>(&op[(size_t)row * HD + col]),
                   make_float2(acc[mt][nt][0], acc[mt][nt][1]));
            __stcg(reinterpret_cast<float2*>(&op[(size_t)(row + 8) * HD + col]),
                   make_float2(acc[mt][nt][2], acc[mt][nt][3]));
        }
    }
}

// ======================= kernel 3: combine (float4) ==============
__global__ void combine_kernel(float* __restrict__ out) {
    const int idx = blockIdx.x * blockDim.x + threadIdx.x;   // over (8192*128)/4
    const int q = idx >> 5;                                  // 32 float4 per row
    float4 acc = make_float4(0.f, 0.f, 0.f, 0.f);
    float l = 0.0f;
#pragma unroll
    for (int s = 0; s < KSPLITS; s++) {
        float4 p = *reinterpret_cast<const float4*>(&g_Opart[s][idx * 4]);
        acc.x += p.x; acc.y += p.y; acc.z += p.z; acc.w += p.w;
        l += g_lpart[s][q];
    }
    float inv = 1.0f / l;
    acc.x *= inv; acc.y *= inv; acc.z *= inv; acc.w *= inv;
    *reinterpret_cast<float4*>(out + idx * 4) = acc;
}

// ======================= launch ==================================
extern "C" void kernel_launch(void* const* d_in, const int* in_sizes, int n_in,
                              void* d_out, int out_size) {
    const float* S  = (const float*)d_in[0];   // [8192, 8192]
    const float* VT = (const float*)d_in[1];   // [128, 8192]
    float* out = (float*)d_out;                // [8192, 128]

    cudaFuncSetAttribute(flash_main_kernel,
                         cudaFuncAttributeMaxDynamicSharedMemorySize, SM_TOTAL);

    convert_v_kernel<<<(HD * SEQ / 4) / 256, 256>>>(VT);   // 1024 blocks
    dim3 grid(SEQ / MT, KSPLITS);
    flash_main_kernel<<<grid, THREADS, SM_TOTAL>>>(S);
    combine_kernel<<<(SEQ * HD / 4) / 256, 256>>>(out);
}